// round 11
// baseline (speedup 1.0000x reference)
#include <cuda_runtime.h>

// Problem constants
#define IMG_H 512
#define IMG_W 512
#define NIMG  64
#define NPIX  (NIMG * IMG_H * IMG_W)   // 16,777,216

#define TILE_W   32
#define TILE_H   64
#define HALO     5
#define SW_H     74          // TILE_H + 2*HALO
#define NTHREADS 512
#define GRID_X   (IMG_W / TILE_W)   // 16
#define GRID_Y   (IMG_H / TILE_H)   // 8
#define NBLOCKS  (GRID_X * GRID_Y * NIMG)   // 8192

// SMEM: mid plane only: 74*32 elems x 16B {(mu1,mu2),(x2+y2,xy)}
#define SMEM_BYTES (SW_H * TILE_W * 16)   // 37,888 -> 3 CTAs/SM (smem-wise even more)

// Separable Gaussian (sigma=1.5, 11 taps), normalized.
#define W0 0.00102838f
#define W1 0.00759876f
#define W2 0.03600077f
#define W3 0.10936060f
#define W4 0.21300553f
#define W5 0.26601172f
__device__ constexpr float GW[11] = {W0, W1, W2, W3, W4, W5, W4, W3, W2, W1, W0};
#define GPI(t) ((t) < 6 ? (t) : 10 - (t))

typedef unsigned long long ull;

__device__ __forceinline__ ull pack2(float lo, float hi) {
    ull d;
    asm("mov.b64 %0, {%1, %2};" : "=l"(d) : "r"(__float_as_uint(lo)), "r"(__float_as_uint(hi)));
    return d;
}
__device__ __forceinline__ void unpack2(ull v, float& lo, float& hi) {
    unsigned r0, r1;
    asm("mov.b64 {%0, %1}, %2;" : "=r"(r0), "=r"(r1) : "l"(v));
    lo = __uint_as_float(r0); hi = __uint_as_float(r1);
}
__device__ __forceinline__ ull fma2(ull a, ull b, ull c) {
    ull d;
    asm("fma.rn.f32x2 %0, %1, %2, %3;" : "=l"(d) : "l"(a), "l"(b), "l"(c));
    return d;
}

__device__ float g_partials[NBLOCKS];
__device__ int   g_count = 0;

extern __shared__ char smem_raw[];

__global__ __launch_bounds__(NTHREADS, 3)
void ssim_fused_kernel(const float* __restrict__ img1, const float* __restrict__ img2,
                       float* __restrict__ out) {
    ulonglong2* midm = (ulonglong2*)smem_raw;   // 74 x 32, {(mu1,mu2),(z,xy)}

    const int tid = threadIdx.x;
    const int img = blockIdx.z;
    const int r0  = blockIdx.y * TILE_H;
    const int c0  = blockIdx.x * TILE_W;
    const float* p1 = img1 + (size_t)img * (IMG_H * IMG_W);
    const float* p2 = img2 + (size_t)img * (IMG_H * IMG_W);

    // Packed Gaussian weight pairs (6 distinct by symmetry)
    ull gp[6];
    gp[0] = pack2(W0, W0); gp[1] = pack2(W1, W1); gp[2] = pack2(W2, W2);
    gp[3] = pack2(W3, W3); gp[4] = pack2(W4, W4); gp[5] = pack2(W5, W5);

    // ---- Horizontal pass, inputs streamed straight from gmem ----
    // unit = (row 0..73, quad tq 0..7) -> output cols cb..cb+3 of mid row.
    // Window: input cols cb-5..cb+8; loaded as float2 pairs cols cb-6..cb+9
    // (2-aligned; each pair uniformly valid or OOB since IMG_W is even).
    for (int unit = tid; unit < SW_H * (TILE_W / 4); unit += NTHREADS) {
        const int row = unit >> 3;
        const int tq  = unit & 7;
        const int cb  = tq * 4;
        const int gr  = r0 + row - HALO;
        const bool rok = (gr >= 0) && (gr < IMG_H);
        const float* rx = p1 + (size_t)gr * IMG_W;
        const float* ry = p2 + (size_t)gr * IMG_W;
        const int base = c0 + cb - 6;

        // v[m] = packed (x,y) for input col (cb-6+m); taps use v[1..14].
        ull v[16];
        #pragma unroll
        for (int m = 0; m < 8; m++) {
            const int gc = base + 2 * m;
            float2 a = make_float2(0.f, 0.f);
            float2 b = make_float2(0.f, 0.f);
            if (rok && gc >= 0 && gc < IMG_W) {
                a = *(const float2*)(rx + gc);
                b = *(const float2*)(ry + gc);
            }
            v[2 * m]     = pack2(a.x, b.x);
            v[2 * m + 1] = pack2(a.y, b.y);
        }

        const int o = row * TILE_W + cb;

        // Sweep A: packed (mu1,mu2) conv
        ull mu[4] = {0, 0, 0, 0};
        #pragma unroll
        for (int k = 1; k < 15; k++) {
            #pragma unroll
            for (int j = 0; j < 4; j++) {
                const int t = k - 1 - j;
                if (t >= 0 && t < 11)
                    mu[j] = fma2(gp[GPI(t)], v[k], mu[j]);
            }
        }
        // Sweep B: packed (z, xy) conv where z = x^2 + y^2
        ull sz[4] = {0, 0, 0, 0};
        #pragma unroll
        for (int k = 1; k < 15; k++) {
            float x, y;
            unpack2(v[k], x, y);
            const float e = x * y;
            const float z = fmaf(x, x, y * y);
            const ull   w = pack2(z, e);
            #pragma unroll
            for (int j = 0; j < 4; j++) {
                const int t = k - 1 - j;
                if (t >= 0 && t < 11)
                    sz[j] = fma2(gp[GPI(t)], w, sz[j]);
            }
        }
        #pragma unroll
        for (int j = 0; j < 4; j++)
            midm[o + j] = make_ulonglong2(mu[j], sz[j]);
    }
    __syncthreads();

    // ---- Vertical pass + SSIM: 16 groups x 32 cols, 4 rows/thread ----
    float local = 0.f;
    const int col = tid & (TILE_W - 1);
    const int rb  = (tid >> 5) * 4;

    const float C1 = 0.0001f;
    const float C2 = 0.0009f;

    {
        ull amu[4] = {0, 0, 0, 0};
        ull asz[4] = {0, 0, 0, 0};

        #pragma unroll
        for (int k = 0; k < 14; k++) {
            const ulonglong2 m = midm[(rb + k) * TILE_W + col];
            #pragma unroll
            for (int j = 0; j < 4; j++) {
                const int t = k - j;
                if (t >= 0 && t < 11) {
                    const ull gpt = gp[GPI(t)];
                    amu[j] = fma2(gpt, m.x, amu[j]);
                    asz[j] = fma2(gpt, m.y, asz[j]);
                }
            }
        }

        #pragma unroll
        for (int j = 0; j < 4; j++) {
            float mu1, mu2, z, exy;
            unpack2(amu[j], mu1, mu2);
            unpack2(asz[j], z, exy);
            const float S   = fmaf(mu1, mu1, mu2 * mu2);   // mu1^2 + mu2^2
            const float P   = mu1 * mu2;
            const float s12 = exy - P;                     // sigma12
            const float sig = z - S;                       // sigma1^2 + sigma2^2
            const float num = (2.f * P + C1) * (2.f * s12 + C2);
            const float den = (S + C1) * (sig + C2);
            local += __fdividef(num, den);
        }
    }

    // ---- Block reduction (fixed order -> deterministic) ----
    #pragma unroll
    for (int off = 16; off > 0; off >>= 1)
        local += __shfl_xor_sync(0xffffffffu, local, off);

    __shared__ float wsum[NTHREADS / 32];
    __shared__ int   s_last;
    if ((tid & 31) == 0) wsum[tid >> 5] = local;
    __syncthreads();
    if (tid == 0) {
        float s = 0.f;
        #pragma unroll
        for (int w = 0; w < NTHREADS / 32; w++) s += wsum[w];
        int bid = (blockIdx.z * gridDim.y + blockIdx.y) * gridDim.x + blockIdx.x;
        g_partials[bid] = s;
        __threadfence();
        int old = atomicAdd(&g_count, 1);
        s_last = (old == NBLOCKS - 1);
    }
    __syncthreads();

    // ---- Last block: deterministic final reduction in fp64, reset counter ----
    if (s_last) {
        __threadfence();
        __shared__ double dsh[NTHREADS / 32];
        double acc = 0.0;
        const int per = NBLOCKS / NTHREADS;   // 16
        for (int i = 0; i < per; i++)
            acc += (double)g_partials[tid * per + i];
        #pragma unroll
        for (int off = 16; off > 0; off >>= 1)
            acc += __shfl_xor_sync(0xffffffffu, acc, off);
        if ((tid & 31) == 0) dsh[tid >> 5] = acc;
        __syncthreads();
        if (tid == 0) {
            double s = 0.0;
            #pragma unroll
            for (int w = 0; w < NTHREADS / 32; w++) s += dsh[w];
            out[0] = (float)(1.0 - s * (1.0 / (double)NPIX));
            g_count = 0;   // reset for next graph replay
        }
    }
}

extern "C" void kernel_launch(void* const* d_in, const int* in_sizes, int n_in,
                              void* d_out, int out_size) {
    const float* pred   = (const float*)d_in[0];
    const float* target = (const float*)d_in[1];
    float* out = (float*)d_out;

    cudaFuncSetAttribute(ssim_fused_kernel,
                         cudaFuncAttributeMaxDynamicSharedMemorySize, SMEM_BYTES);

    dim3 grid(GRID_X, GRID_Y, NIMG);   // (16, 8, 64)
    ssim_fused_kernel<<<grid, NTHREADS, SMEM_BYTES>>>(pred, target, out);
}

// round 12
// speedup vs baseline: 1.5801x; 1.5801x over previous
#include <cuda_runtime.h>
#include <cuda_fp16.h>

// Problem constants
#define IMG_H 512
#define IMG_W 512
#define NIMG  64
#define NPIX  (NIMG * IMG_H * IMG_W)   // 16,777,216

#define TILE_W   32
#define TILE_H   64
#define HALO     5
#define SW_H     74          // TILE_H + 2*HALO
#define PAD_L    8           // left pad (>= HALO, quad aligned)
#define XY_W     48          // strip width in packed elems (12 quads)
#define NTHREADS 512
#define GRID_X   (IMG_W / TILE_W)   // 16
#define GRID_Y   (IMG_H / TILE_H)   // 8
#define NBLOCKS  (GRID_X * GRID_Y * NIMG)   // 8192

// SMEM layout (bytes):
//  xy  : 74*48*8 = 28416   packed f32 (x,y) inputs
//  mid : 74*32*8 = 18944   4 x fp16 {mu1,mu2,z,xy} per elem (uint2)
#define XY_BYTES   (SW_H * XY_W * 8)
#define SMEM_BYTES (XY_BYTES + SW_H * TILE_W * 8)   // 47,360 -> 3 CTAs/SM
// (3 CTAs kept via launch_bounds; 4 would cap regs at 32 and spill)

// Separable Gaussian (sigma=1.5, 11 taps), normalized.
#define W0 0.00102838f
#define W1 0.00759876f
#define W2 0.03600077f
#define W3 0.10936060f
#define W4 0.21300553f
#define W5 0.26601172f
__device__ constexpr float GW[11] = {W0, W1, W2, W3, W4, W5, W4, W3, W2, W1, W0};
#define GPI(t) ((t) < 6 ? (t) : 10 - (t))

typedef unsigned long long ull;

__device__ __forceinline__ ull pack2(float lo, float hi) {
    ull d;
    asm("mov.b64 %0, {%1, %2};" : "=l"(d) : "r"(__float_as_uint(lo)), "r"(__float_as_uint(hi)));
    return d;
}
__device__ __forceinline__ void unpack2(ull v, float& lo, float& hi) {
    unsigned r0, r1;
    asm("mov.b64 {%0, %1}, %2;" : "=r"(r0), "=r"(r1) : "l"(v));
    lo = __uint_as_float(r0); hi = __uint_as_float(r1);
}
__device__ __forceinline__ ull fma2(ull a, ull b, ull c) {
    ull d;
    asm("fma.rn.f32x2 %0, %1, %2, %3;" : "=l"(d) : "l"(a), "l"(b), "l"(c));
    return d;
}
// f32x2 (packed in ull) -> f16x2 (one 32-bit reg)
__device__ __forceinline__ unsigned cvt_h2(ull v) {
    float lo, hi;
    unpack2(v, lo, hi);
    unsigned r;
    asm("cvt.rn.f16x2.f32 %0, %1, %2;" : "=r"(r) : "f"(hi), "f"(lo));
    return r;
}

__device__ float g_partials[NBLOCKS];
__device__ int   g_count = 0;

extern __shared__ char smem_raw[];

__global__ __launch_bounds__(NTHREADS, 3)
void ssim_fused_kernel(const float* __restrict__ img1, const float* __restrict__ img2,
                       float* __restrict__ out) {
    ull*   xy   = (ull*)smem_raw;                    // 74 x 48 packed f32 (x,y)
    uint2* midh = (uint2*)(smem_raw + XY_BYTES);     // 74 x 32, {h2(mu1,mu2), h2(z,xy)}

    const int tid = threadIdx.x;
    const int img = blockIdx.z;
    const int r0  = blockIdx.y * TILE_H;
    const int c0  = blockIdx.x * TILE_W;
    const float* p1 = img1 + (size_t)img * (IMG_H * IMG_W);
    const float* p2 = img2 + (size_t)img * (IMG_H * IMG_W);

    // Packed Gaussian weight pairs (6 distinct by symmetry)
    ull gp[6];
    gp[0] = pack2(W0, W0); gp[1] = pack2(W1, W1); gp[2] = pack2(W2, W2);
    gp[3] = pack2(W3, W3); gp[4] = pack2(W4, W4); gp[5] = pack2(W5, W5);

    // ---- Load halo strip: unit = (row, quad of 4 cols) ----
    for (int u = tid; u < SW_H * (XY_W / 4); u += NTHREADS) {
        int r = u / (XY_W / 4);
        int q = u - r * (XY_W / 4);
        int gr = r0 + r - HALO;
        int gc = c0 - PAD_L + q * 4;
        float4 vx = make_float4(0.f, 0.f, 0.f, 0.f);
        float4 vy = vx;
        if (gr >= 0 && gr < IMG_H && gc >= 0 && gc + 3 < IMG_W) {
            vx = *(const float4*)(p1 + (size_t)gr * IMG_W + gc);
            vy = *(const float4*)(p2 + (size_t)gr * IMG_W + gc);
        }
        ulonglong2* dst = (ulonglong2*)(xy + r * XY_W + q * 4);
        dst[0] = make_ulonglong2(pack2(vx.x, vy.x), pack2(vx.y, vy.y));
        dst[1] = make_ulonglong2(pack2(vx.z, vy.z), pack2(vx.w, vy.w));
    }
    __syncthreads();

    // ---- Horizontal pass: unit = (row, 4 output cols); 74*8 = 592 units ----
    for (int unit = tid; unit < SW_H * (TILE_W / 4); unit += NTHREADS) {
        int row = unit >> 3;
        int cb  = (unit & 7) * 4;

        // Needed input col n lives at smem col n + (PAD_L - HALO) = n + 3.
        // Load 16 packed starting at smem col cb+2 (16B aligned); use v[1..14].
        ull v[16];
        const ulonglong2* vr = (const ulonglong2*)(xy + row * XY_W + cb + 2);
        #pragma unroll
        for (int i = 0; i < 8; i++) {
            ulonglong2 t = vr[i];
            v[2 * i]     = t.x;
            v[2 * i + 1] = t.y;
        }

        // Sweep A: packed (mu1,mu2) conv
        ull mu[4] = {0, 0, 0, 0};
        #pragma unroll
        for (int k = 1; k < 15; k++) {
            #pragma unroll
            for (int j = 0; j < 4; j++) {
                const int t = k - 1 - j;
                if (t >= 0 && t < 11)
                    mu[j] = fma2(gp[GPI(t)], v[k], mu[j]);
            }
        }
        // Sweep B: packed (z, xy) conv where z = x^2 + y^2
        ull sz[4] = {0, 0, 0, 0};
        #pragma unroll
        for (int k = 1; k < 15; k++) {
            float x, y;
            unpack2(v[k], x, y);
            const float e = x * y;
            const float z = fmaf(x, x, y * y);
            const ull   w = pack2(z, e);
            #pragma unroll
            for (int j = 0; j < 4; j++) {
                const int t = k - 1 - j;
                if (t >= 0 && t < 11)
                    sz[j] = fma2(gp[GPI(t)], w, sz[j]);
            }
        }
        // fp16 stores: 2 outputs per STS.128 (o % 4 == 0 -> 32B aligned)
        const int o = row * TILE_W + cb;
        uint4* dst = (uint4*)(midh + o);
        dst[0] = make_uint4(cvt_h2(mu[0]), cvt_h2(sz[0]), cvt_h2(mu[1]), cvt_h2(sz[1]));
        dst[1] = make_uint4(cvt_h2(mu[2]), cvt_h2(sz[2]), cvt_h2(mu[3]), cvt_h2(sz[3]));
    }
    __syncthreads();

    // ---- Vertical pass + SSIM: 16 groups x 32 cols, 4 rows/thread ----
    float local = 0.f;
    const int col = tid & (TILE_W - 1);
    const int rb  = (tid >> 5) * 4;

    const float C1 = 0.0001f;
    const float C2 = 0.0009f;

    {
        float m1[4] = {0,0,0,0};
        float m2[4] = {0,0,0,0};
        float az[4] = {0,0,0,0};
        float ae[4] = {0,0,0,0};

        #pragma unroll
        for (int k = 0; k < 14; k++) {
            const uint2 m = midh[(rb + k) * TILE_W + col];      // LDS.64
            const float2 mv = __half22float2(*(const __half2*)&m.x);
            const float2 sv = __half22float2(*(const __half2*)&m.y);
            #pragma unroll
            for (int j = 0; j < 4; j++) {
                const int t = k - j;
                if (t >= 0 && t < 11) {   // FFMA-imm chains (GW literal)
                    m1[j] = fmaf(GW[t], mv.x, m1[j]);
                    m2[j] = fmaf(GW[t], mv.y, m2[j]);
                    az[j] = fmaf(GW[t], sv.x, az[j]);
                    ae[j] = fmaf(GW[t], sv.y, ae[j]);
                }
            }
        }

        #pragma unroll
        for (int j = 0; j < 4; j++) {
            const float mu1 = m1[j], mu2 = m2[j];
            const float S   = fmaf(mu1, mu1, mu2 * mu2);   // mu1^2 + mu2^2
            const float P   = mu1 * mu2;
            const float s12 = ae[j] - P;                   // sigma12
            const float sig = az[j] - S;                   // sigma1^2 + sigma2^2
            const float num = (2.f * P + C1) * (2.f * s12 + C2);
            const float den = (S + C1) * (sig + C2);
            local += __fdividef(num, den);
        }
    }

    // ---- Block reduction (fixed order -> deterministic) ----
    #pragma unroll
    for (int off = 16; off > 0; off >>= 1)
        local += __shfl_xor_sync(0xffffffffu, local, off);

    __shared__ float wsum[NTHREADS / 32];
    __shared__ int   s_last;
    if ((tid & 31) == 0) wsum[tid >> 5] = local;
    __syncthreads();
    if (tid == 0) {
        float s = 0.f;
        #pragma unroll
        for (int w = 0; w < NTHREADS / 32; w++) s += wsum[w];
        int bid = (blockIdx.z * gridDim.y + blockIdx.y) * gridDim.x + blockIdx.x;
        g_partials[bid] = s;
        __threadfence();
        int old = atomicAdd(&g_count, 1);
        s_last = (old == NBLOCKS - 1);
    }
    __syncthreads();

    // ---- Last block: deterministic final reduction in fp64, reset counter ----
    if (s_last) {
        __threadfence();
        __shared__ double dsh[NTHREADS / 32];
        double acc = 0.0;
        const int per = NBLOCKS / NTHREADS;   // 16
        for (int i = 0; i < per; i++)
            acc += (double)g_partials[tid * per + i];
        #pragma unroll
        for (int off = 16; off > 0; off >>= 1)
            acc += __shfl_xor_sync(0xffffffffu, acc, off);
        if ((tid & 31) == 0) dsh[tid >> 5] = acc;
        __syncthreads();
        if (tid == 0) {
            double s = 0.0;
            #pragma unroll
            for (int w = 0; w < NTHREADS / 32; w++) s += dsh[w];
            out[0] = (float)(1.0 - s * (1.0 / (double)NPIX));
            g_count = 0;   // reset for next graph replay
        }
    }
}

extern "C" void kernel_launch(void* const* d_in, const int* in_sizes, int n_in,
                              void* d_out, int out_size) {
    const float* pred   = (const float*)d_in[0];
    const float* target = (const float*)d_in[1];
    float* out = (float*)d_out;

    cudaFuncSetAttribute(ssim_fused_kernel,
                         cudaFuncAttributeMaxDynamicSharedMemorySize, SMEM_BYTES);

    dim3 grid(GRID_X, GRID_Y, NIMG);   // (16, 8, 64)
    ssim_fused_kernel<<<grid, NTHREADS, SMEM_BYTES>>>(pred, target, out);
}

// round 13
// speedup vs baseline: 1.9333x; 1.2235x over previous
#include <cuda_runtime.h>
#include <cuda_fp16.h>

// Problem constants
#define IMG_H 512
#define IMG_W 512
#define NIMG  64
#define NPIX  (NIMG * IMG_H * IMG_W)   // 16,777,216

#define TILE_W   32
#define TILE_H   128
#define HALO     5
#define SW_H     138         // TILE_H + 2*HALO
#define PAD_L    8           // left pad (>= HALO, quad aligned)
#define XY_W     48          // strip width in elems (12 quads); 48 = 8+32+8
#define NTHREADS 512
#define GRID_X   (IMG_W / TILE_W)   // 16
#define GRID_Y   (IMG_H / TILE_H)   // 4
#define NBLOCKS  (GRID_X * GRID_Y * NIMG)   // 4096

// SMEM layout (bytes):
//  xyh : 138*48*4 = 26496   half2(x,y) inputs
//  pmu : 138*32*4 = 17664   half2(mu1,mu2) plane
//  pze : 138*32*4 = 17664   half2(z,xy) plane, z = x^2+y^2
#define XYH_BYTES  (SW_H * XY_W * 4)
#define PMU_BYTES  (SW_H * TILE_W * 4)
#define SMEM_BYTES (XYH_BYTES + 2 * PMU_BYTES)   // 61,824 -> 3 CTAs/SM

// Separable Gaussian (sigma=1.5, 11 taps), normalized.
#define W0 0.00102838f
#define W1 0.00759876f
#define W2 0.03600077f
#define W3 0.10936060f
#define W4 0.21300553f
#define W5 0.26601172f
__device__ constexpr float GW[11] = {W0, W1, W2, W3, W4, W5, W4, W3, W2, W1, W0};
#define GPI(t) ((t) < 6 ? (t) : 10 - (t))

typedef unsigned long long ull;

__device__ __forceinline__ ull pack2(float lo, float hi) {
    ull d;
    asm("mov.b64 %0, {%1, %2};" : "=l"(d) : "r"(__float_as_uint(lo)), "r"(__float_as_uint(hi)));
    return d;
}
__device__ __forceinline__ void unpack2(ull v, float& lo, float& hi) {
    unsigned r0, r1;
    asm("mov.b64 {%0, %1}, %2;" : "=r"(r0), "=r"(r1) : "l"(v));
    lo = __uint_as_float(r0); hi = __uint_as_float(r1);
}
__device__ __forceinline__ ull fma2(ull a, ull b, ull c) {
    ull d;
    asm("fma.rn.f32x2 %0, %1, %2, %3;" : "=l"(d) : "l"(a), "l"(b), "l"(c));
    return d;
}
// (lo, hi) floats -> f16x2 in one 32-bit reg (same convention as R12: %1=hi, %2=lo)
__device__ __forceinline__ unsigned h2pack(float lo, float hi) {
    unsigned r;
    asm("cvt.rn.f16x2.f32 %0, %1, %2;" : "=r"(r) : "f"(hi), "f"(lo));
    return r;
}
// f32x2 (ull) -> f16x2
__device__ __forceinline__ unsigned cvt_h2(ull v) {
    float lo, hi;
    unpack2(v, lo, hi);
    return h2pack(lo, hi);
}
__device__ __forceinline__ float2 h2unpack(unsigned r) {
    return __half22float2(*(const __half2*)&r);
}

__device__ float g_partials[NBLOCKS];
__device__ int   g_count = 0;

extern __shared__ char smem_raw[];

__global__ __launch_bounds__(NTHREADS, 3)
void ssim_fused_kernel(const float* __restrict__ img1, const float* __restrict__ img2,
                       float* __restrict__ out) {
    unsigned* xyh = (unsigned*)smem_raw;                             // 138 x 48 half2(x,y)
    unsigned* pmu = (unsigned*)(smem_raw + XYH_BYTES);               // 138 x 32 half2(mu1,mu2)
    unsigned* pze = (unsigned*)(smem_raw + XYH_BYTES + PMU_BYTES);   // 138 x 32 half2(z,xy)

    const int tid = threadIdx.x;
    const int img = blockIdx.z;
    const int r0  = blockIdx.y * TILE_H;
    const int c0  = blockIdx.x * TILE_W;
    const float* p1 = img1 + (size_t)img * (IMG_H * IMG_W);
    const float* p2 = img2 + (size_t)img * (IMG_H * IMG_W);

    // Packed Gaussian weight pairs for f32x2 horizontal conv
    ull gp[6];
    gp[0] = pack2(W0, W0); gp[1] = pack2(W1, W1); gp[2] = pack2(W2, W2);
    gp[3] = pack2(W3, W3); gp[4] = pack2(W4, W4); gp[5] = pack2(W5, W5);

    // ---- Load halo strip as half2(x,y): unit = (row, quad of 4 cols) ----
    // Strip covers global cols [c0-8, c0+40); quads uniformly valid or OOB.
    for (int u = tid; u < SW_H * (XY_W / 4); u += NTHREADS) {
        int r = u / (XY_W / 4);
        int q = u - r * (XY_W / 4);
        int gr = r0 + r - HALO;
        int gc = c0 - PAD_L + q * 4;
        float4 vx = make_float4(0.f, 0.f, 0.f, 0.f);
        float4 vy = vx;
        if (gr >= 0 && gr < IMG_H && gc >= 0 && gc + 3 < IMG_W) {
            vx = *(const float4*)(p1 + (size_t)gr * IMG_W + gc);
            vy = *(const float4*)(p2 + (size_t)gr * IMG_W + gc);
        }
        *(uint4*)(xyh + r * XY_W + q * 4) =
            make_uint4(h2pack(vx.x, vy.x), h2pack(vx.y, vy.y),
                       h2pack(vx.z, vy.z), h2pack(vx.w, vy.w));
    }
    __syncthreads();

    // ---- Horizontal pass: unit = (row, 4 output cols); 138*8 = 1104 units ----
    // Smem col s holds input col s-8 (tile-relative). Output j (col cb+j) taps
    // inputs cb+j-5..cb+j+5 -> smem cols cb+j+3..cb+j+13. Load cols cb..cb+19
    // (5x LDS.128, 16B aligned), use k = 3..16 with t = k-3-j.
    for (int unit = tid; unit < SW_H * (TILE_W / 4); unit += NTHREADS) {
        const int row = unit >> 3;
        const int cb  = (unit & 7) * 4;

        unsigned u[20];
        const uint4* vr = (const uint4*)(xyh + row * XY_W + cb);
        #pragma unroll
        for (int i = 0; i < 5; i++) {
            uint4 t = vr[i];
            u[4*i+0] = t.x; u[4*i+1] = t.y; u[4*i+2] = t.z; u[4*i+3] = t.w;
        }

        const int o = row * TILE_W + cb;

        // Sweep A: packed (mu1,mu2) conv
        {
            ull mu[4] = {0, 0, 0, 0};
            #pragma unroll
            for (int k = 3; k < 17; k++) {
                const float2 f = h2unpack(u[k]);
                const ull w = pack2(f.x, f.y);
                #pragma unroll
                for (int j = 0; j < 4; j++) {
                    const int t = k - 3 - j;
                    if (t >= 0 && t < 11)
                        mu[j] = fma2(gp[GPI(t)], w, mu[j]);
                }
            }
            *(uint4*)(pmu + o) = make_uint4(cvt_h2(mu[0]), cvt_h2(mu[1]),
                                            cvt_h2(mu[2]), cvt_h2(mu[3]));
        }
        // Sweep B: packed (z, xy) conv, z = x^2 + y^2
        {
            ull sz[4] = {0, 0, 0, 0};
            #pragma unroll
            for (int k = 3; k < 17; k++) {
                const float2 f = h2unpack(u[k]);
                const float e = f.x * f.y;
                const float z = fmaf(f.x, f.x, f.y * f.y);
                const ull w = pack2(z, e);
                #pragma unroll
                for (int j = 0; j < 4; j++) {
                    const int t = k - 3 - j;
                    if (t >= 0 && t < 11)
                        sz[j] = fma2(gp[GPI(t)], w, sz[j]);
                }
            }
            *(uint4*)(pze + o) = make_uint4(cvt_h2(sz[0]), cvt_h2(sz[1]),
                                            cvt_h2(sz[2]), cvt_h2(sz[3]));
        }
    }
    __syncthreads();

    // ---- Vertical pass + SSIM: 16 groups x 32 cols, 8 rows/thread, all active ----
    float local = 0.f;
    const int col = tid & (TILE_W - 1);
    const int rb  = (tid >> 5) * 8;     // output rows rb..rb+7; taps rb..rb+17

    const float C1 = 0.0001f;
    const float C2 = 0.0009f;

    {
        float m1[8] = {0,0,0,0,0,0,0,0};
        float m2[8] = {0,0,0,0,0,0,0,0};
        #pragma unroll
        for (int k = 0; k < 18; k++) {
            const float2 mv = h2unpack(pmu[(rb + k) * TILE_W + col]);   // LDS.32, 1 wf
            #pragma unroll
            for (int j = 0; j < 8; j++) {
                const int t = k - j;
                if (t >= 0 && t < 11) {   // FFMA-imm chains
                    m1[j] = fmaf(GW[t], mv.x, m1[j]);
                    m2[j] = fmaf(GW[t], mv.y, m2[j]);
                }
            }
        }

        float az[8] = {0,0,0,0,0,0,0,0};
        float ae[8] = {0,0,0,0,0,0,0,0};
        #pragma unroll
        for (int k = 0; k < 18; k++) {
            const float2 sv = h2unpack(pze[(rb + k) * TILE_W + col]);
            #pragma unroll
            for (int j = 0; j < 8; j++) {
                const int t = k - j;
                if (t >= 0 && t < 11) {
                    az[j] = fmaf(GW[t], sv.x, az[j]);
                    ae[j] = fmaf(GW[t], sv.y, ae[j]);
                }
            }
        }

        #pragma unroll
        for (int j = 0; j < 8; j++) {
            const float mu1 = m1[j], mu2 = m2[j];
            const float S   = fmaf(mu1, mu1, mu2 * mu2);   // mu1^2 + mu2^2
            const float P   = mu1 * mu2;
            const float s12 = ae[j] - P;                   // sigma12
            const float sig = az[j] - S;                   // sigma1^2 + sigma2^2
            const float num = (2.f * P + C1) * (2.f * s12 + C2);
            const float den = (S + C1) * (sig + C2);
            local += __fdividef(num, den);
        }
    }

    // ---- Block reduction (fixed order -> deterministic) ----
    #pragma unroll
    for (int off = 16; off > 0; off >>= 1)
        local += __shfl_xor_sync(0xffffffffu, local, off);

    __shared__ float wsum[NTHREADS / 32];
    __shared__ int   s_last;
    if ((tid & 31) == 0) wsum[tid >> 5] = local;
    __syncthreads();
    if (tid == 0) {
        float s = 0.f;
        #pragma unroll
        for (int w = 0; w < NTHREADS / 32; w++) s += wsum[w];
        int bid = (blockIdx.z * gridDim.y + blockIdx.y) * gridDim.x + blockIdx.x;
        g_partials[bid] = s;
        __threadfence();
        int old = atomicAdd(&g_count, 1);
        s_last = (old == NBLOCKS - 1);
    }
    __syncthreads();

    // ---- Last block: deterministic final reduction in fp64, reset counter ----
    if (s_last) {
        __threadfence();
        __shared__ double dsh[NTHREADS / 32];
        double acc = 0.0;
        const int per = NBLOCKS / NTHREADS;   // 8
        for (int i = 0; i < per; i++)
            acc += (double)g_partials[tid * per + i];
        #pragma unroll
        for (int off = 16; off > 0; off >>= 1)
            acc += __shfl_xor_sync(0xffffffffu, acc, off);
        if ((tid & 31) == 0) dsh[tid >> 5] = acc;
        __syncthreads();
        if (tid == 0) {
            double s = 0.0;
            #pragma unroll
            for (int w = 0; w < NTHREADS / 32; w++) s += dsh[w];
            out[0] = (float)(1.0 - s * (1.0 / (double)NPIX));
            g_count = 0;   // reset for next graph replay
        }
    }
}

extern "C" void kernel_launch(void* const* d_in, const int* in_sizes, int n_in,
                              void* d_out, int out_size) {
    const float* pred   = (const float*)d_in[0];
    const float* target = (const float*)d_in[1];
    float* out = (float*)d_out;

    cudaFuncSetAttribute(ssim_fused_kernel,
                         cudaFuncAttributeMaxDynamicSharedMemorySize, SMEM_BYTES);

    dim3 grid(GRID_X, GRID_Y, NIMG);   // (16, 4, 64)
    ssim_fused_kernel<<<grid, NTHREADS, SMEM_BYTES>>>(pred, target, out);
}

// round 14
// speedup vs baseline: 2.0196x; 1.0447x over previous
#include <cuda_runtime.h>
#include <cuda_fp16.h>

// Problem constants
#define IMG_H 512
#define IMG_W 512
#define NIMG  64
#define NPIX  (NIMG * IMG_H * IMG_W)   // 16,777,216

#define TILE_W   32
#define TILE_H   128
#define HALO     5
#define SW_H     138         // TILE_H + 2*HALO
#define PAD_L    8           // left pad (>= HALO, quad aligned)
#define XY_W     48          // strip width in elems (12 quads); 48 = 8+32+8
#define NTHREADS 512
#define GRID_X   (IMG_W / TILE_W)   // 16
#define GRID_Y   (IMG_H / TILE_H)   // 4
#define NBLOCKS  (GRID_X * GRID_Y * NIMG)   // 4096

// SMEM layout (bytes):
//  xyh : 138*48*4 = 26496   half2(x,y) inputs
//  pmu : 138*32*4 = 17664   half2(mu1,mu2) plane
//  pze : 138*32*4 = 17664   half2(z,xy) plane, z = x^2+y^2
#define XYH_BYTES  (SW_H * XY_W * 4)
#define PMU_BYTES  (SW_H * TILE_W * 4)
#define SMEM_BYTES (XYH_BYTES + 2 * PMU_BYTES)   // 61,824 -> 3 CTAs/SM

// Separable Gaussian (sigma=1.5, 11 taps), normalized.
#define W0 0.00102838f
#define W1 0.00759876f
#define W2 0.03600077f
#define W3 0.10936060f
#define W4 0.21300553f
#define W5 0.26601172f
__device__ constexpr float GW[11] = {W0, W1, W2, W3, W4, W5, W4, W3, W2, W1, W0};
#define GPI(t) ((t) < 6 ? (t) : 10 - (t))

typedef unsigned long long ull;

__device__ __forceinline__ ull pack2(float lo, float hi) {
    ull d;
    asm("mov.b64 %0, {%1, %2};" : "=l"(d) : "r"(__float_as_uint(lo)), "r"(__float_as_uint(hi)));
    return d;
}
__device__ __forceinline__ void unpack2(ull v, float& lo, float& hi) {
    unsigned r0, r1;
    asm("mov.b64 {%0, %1}, %2;" : "=r"(r0), "=r"(r1) : "l"(v));
    lo = __uint_as_float(r0); hi = __uint_as_float(r1);
}
__device__ __forceinline__ ull fma2(ull a, ull b, ull c) {
    ull d;
    asm("fma.rn.f32x2 %0, %1, %2, %3;" : "=l"(d) : "l"(a), "l"(b), "l"(c));
    return d;
}
// (lo, hi) floats -> f16x2 in one 32-bit reg
__device__ __forceinline__ unsigned h2pack(float lo, float hi) {
    unsigned r;
    asm("cvt.rn.f16x2.f32 %0, %1, %2;" : "=r"(r) : "f"(hi), "f"(lo));
    return r;
}
// f32x2 (ull) -> f16x2
__device__ __forceinline__ unsigned cvt_h2(ull v) {
    float lo, hi;
    unpack2(v, lo, hi);
    return h2pack(lo, hi);
}
__device__ __forceinline__ float2 h2unpack(unsigned r) {
    return __half22float2(*(const __half2*)&r);
}
// f16x2 -> packed f32x2 (ull)
__device__ __forceinline__ ull h2_to_p2(unsigned r) {
    const float2 f = h2unpack(r);
    return pack2(f.x, f.y);
}

__device__ float g_partials[NBLOCKS];
__device__ int   g_count = 0;

extern __shared__ char smem_raw[];

__global__ __launch_bounds__(NTHREADS, 3)
void ssim_fused_kernel(const float* __restrict__ img1, const float* __restrict__ img2,
                       float* __restrict__ out) {
    unsigned* xyh = (unsigned*)smem_raw;                             // 138 x 48 half2(x,y)
    unsigned* pmu = (unsigned*)(smem_raw + XYH_BYTES);               // 138 x 32 half2(mu1,mu2)
    unsigned* pze = (unsigned*)(smem_raw + XYH_BYTES + PMU_BYTES);   // 138 x 32 half2(z,xy)

    const int tid = threadIdx.x;
    const int img = blockIdx.z;
    const int r0  = blockIdx.y * TILE_H;
    const int c0  = blockIdx.x * TILE_W;
    const float* p1 = img1 + (size_t)img * (IMG_H * IMG_W);
    const float* p2 = img2 + (size_t)img * (IMG_H * IMG_W);

    // Packed Gaussian weight pairs for f32x2 conv (both passes)
    ull gp[6];
    gp[0] = pack2(W0, W0); gp[1] = pack2(W1, W1); gp[2] = pack2(W2, W2);
    gp[3] = pack2(W3, W3); gp[4] = pack2(W4, W4); gp[5] = pack2(W5, W5);

    // ---- Load halo strip as half2(x,y): unit = (row, quad of 4 cols) ----
    for (int u = tid; u < SW_H * (XY_W / 4); u += NTHREADS) {
        int r = u / (XY_W / 4);
        int q = u - r * (XY_W / 4);
        int gr = r0 + r - HALO;
        int gc = c0 - PAD_L + q * 4;
        float4 vx = make_float4(0.f, 0.f, 0.f, 0.f);
        float4 vy = vx;
        if (gr >= 0 && gr < IMG_H && gc >= 0 && gc + 3 < IMG_W) {
            vx = *(const float4*)(p1 + (size_t)gr * IMG_W + gc);
            vy = *(const float4*)(p2 + (size_t)gr * IMG_W + gc);
        }
        *(uint4*)(xyh + r * XY_W + q * 4) =
            make_uint4(h2pack(vx.x, vy.x), h2pack(vx.y, vy.y),
                       h2pack(vx.z, vy.z), h2pack(vx.w, vy.w));
    }
    __syncthreads();

    // ---- Horizontal pass: unit = (row, 4 output cols); 138*8 = 1104 units ----
    // Smem col s holds input col s-8. Output j (col cb+j) taps smem cols
    // cb+j+3..cb+j+13. Load cols cb..cb+19 (5x LDS.128), use k=3..16, t=k-3-j.
    for (int unit = tid; unit < SW_H * (TILE_W / 4); unit += NTHREADS) {
        const int row = unit >> 3;
        const int cb  = (unit & 7) * 4;

        unsigned u[20];
        const uint4* vr = (const uint4*)(xyh + row * XY_W + cb);
        #pragma unroll
        for (int i = 0; i < 5; i++) {
            uint4 t = vr[i];
            u[4*i+0] = t.x; u[4*i+1] = t.y; u[4*i+2] = t.z; u[4*i+3] = t.w;
        }

        const int o = row * TILE_W + cb;

        // Sweep A: packed (mu1,mu2) conv
        {
            ull mu[4] = {0, 0, 0, 0};
            #pragma unroll
            for (int k = 3; k < 17; k++) {
                const ull w = h2_to_p2(u[k]);
                #pragma unroll
                for (int j = 0; j < 4; j++) {
                    const int t = k - 3 - j;
                    if (t >= 0 && t < 11)
                        mu[j] = fma2(gp[GPI(t)], w, mu[j]);
                }
            }
            *(uint4*)(pmu + o) = make_uint4(cvt_h2(mu[0]), cvt_h2(mu[1]),
                                            cvt_h2(mu[2]), cvt_h2(mu[3]));
        }
        // Sweep B: packed (z, xy) conv, z = x^2 + y^2
        {
            ull sz[4] = {0, 0, 0, 0};
            #pragma unroll
            for (int k = 3; k < 17; k++) {
                const float2 f = h2unpack(u[k]);
                const float e = f.x * f.y;
                const float z = fmaf(f.x, f.x, f.y * f.y);
                const ull w = pack2(z, e);
                #pragma unroll
                for (int j = 0; j < 4; j++) {
                    const int t = k - 3 - j;
                    if (t >= 0 && t < 11)
                        sz[j] = fma2(gp[GPI(t)], w, sz[j]);
                }
            }
            *(uint4*)(pze + o) = make_uint4(cvt_h2(sz[0]), cvt_h2(sz[1]),
                                            cvt_h2(sz[2]), cvt_h2(sz[3]));
        }
    }
    __syncthreads();

    // ---- Vertical pass + SSIM: 16 groups x 32 cols, 8 rows/thread ----
    // Both chains of each sweep packed into f32x2 FMAs (halves vertical instr count).
    float local = 0.f;
    const int col = tid & (TILE_W - 1);
    const int rb  = (tid >> 5) * 8;     // output rows rb..rb+7; taps rb..rb+17

    const float C1 = 0.0001f;
    const float C2 = 0.0009f;

    {
        // Sweep 1: (mu1,mu2) packed accumulation -> fold to P, S
        float P[8], S[8];
        {
            ull amu[8] = {0,0,0,0,0,0,0,0};
            #pragma unroll
            for (int k = 0; k < 18; k++) {
                const ull w = h2_to_p2(pmu[(rb + k) * TILE_W + col]);
                #pragma unroll
                for (int j = 0; j < 8; j++) {
                    const int t = k - j;
                    if (t >= 0 && t < 11)
                        amu[j] = fma2(gp[GPI(t)], w, amu[j]);
                }
            }
            #pragma unroll
            for (int j = 0; j < 8; j++) {
                float mu1, mu2;
                unpack2(amu[j], mu1, mu2);
                P[j] = mu1 * mu2;
                S[j] = fmaf(mu1, mu1, mu2 * mu2);
            }
        }

        // Sweep 2: (z, xy) packed accumulation -> SSIM
        {
            ull asz[8] = {0,0,0,0,0,0,0,0};
            #pragma unroll
            for (int k = 0; k < 18; k++) {
                const ull w = h2_to_p2(pze[(rb + k) * TILE_W + col]);
                #pragma unroll
                for (int j = 0; j < 8; j++) {
                    const int t = k - j;
                    if (t >= 0 && t < 11)
                        asz[j] = fma2(gp[GPI(t)], w, asz[j]);
                }
            }
            #pragma unroll
            for (int j = 0; j < 8; j++) {
                float z, e;
                unpack2(asz[j], z, e);
                const float s12 = e - P[j];                // sigma12
                const float sig = z - S[j];                // sigma1^2 + sigma2^2
                const float num = (2.f * P[j] + C1) * (2.f * s12 + C2);
                const float den = (S[j] + C1) * (sig + C2);
                local += __fdividef(num, den);
            }
        }
    }

    // ---- Block reduction (fixed order -> deterministic) ----
    #pragma unroll
    for (int off = 16; off > 0; off >>= 1)
        local += __shfl_xor_sync(0xffffffffu, local, off);

    __shared__ float wsum[NTHREADS / 32];
    __shared__ int   s_last;
    if ((tid & 31) == 0) wsum[tid >> 5] = local;
    __syncthreads();
    if (tid == 0) {
        float s = 0.f;
        #pragma unroll
        for (int w = 0; w < NTHREADS / 32; w++) s += wsum[w];
        int bid = (blockIdx.z * gridDim.y + blockIdx.y) * gridDim.x + blockIdx.x;
        g_partials[bid] = s;
        __threadfence();
        int old = atomicAdd(&g_count, 1);
        s_last = (old == NBLOCKS - 1);
    }
    __syncthreads();

    // ---- Last block: deterministic final reduction in fp64, reset counter ----
    if (s_last) {
        __threadfence();
        __shared__ double dsh[NTHREADS / 32];
        double acc = 0.0;
        const int per = NBLOCKS / NTHREADS;   // 8
        for (int i = 0; i < per; i++)
            acc += (double)g_partials[tid * per + i];
        #pragma unroll
        for (int off = 16; off > 0; off >>= 1)
            acc += __shfl_xor_sync(0xffffffffu, acc, off);
        if ((tid & 31) == 0) dsh[tid >> 5] = acc;
        __syncthreads();
        if (tid == 0) {
            double s = 0.0;
            #pragma unroll
            for (int w = 0; w < NTHREADS / 32; w++) s += dsh[w];
            out[0] = (float)(1.0 - s * (1.0 / (double)NPIX));
            g_count = 0;   // reset for next graph replay
        }
    }
}

extern "C" void kernel_launch(void* const* d_in, const int* in_sizes, int n_in,
                              void* d_out, int out_size) {
    const float* pred   = (const float*)d_in[0];
    const float* target = (const float*)d_in[1];
    float* out = (float*)d_out;

    cudaFuncSetAttribute(ssim_fused_kernel,
                         cudaFuncAttributeMaxDynamicSharedMemorySize, SMEM_BYTES);

    dim3 grid(GRID_X, GRID_Y, NIMG);   // (16, 4, 64)
    ssim_fused_kernel<<<grid, NTHREADS, SMEM_BYTES>>>(pred, target, out);
}

// round 15
// speedup vs baseline: 2.1014x; 1.0405x over previous
#include <cuda_runtime.h>

// Problem constants
#define IMG_H 512
#define IMG_W 512
#define NIMG  64
#define NPIX  (NIMG * IMG_H * IMG_W)   // 16,777,216

#define TILE_W   32
#define TILE_H   128
#define HALO     5
#define SW_H     138         // TILE_H + 2*HALO
#define PAD_L    8           // left pad (>= HALO, quad aligned)
#define XY_W     48          // strip width in elems (12 quads)
#define NTHREADS 512
#define GRID_X   (IMG_W / TILE_W)   // 16
#define GRID_Y   (IMG_H / TILE_H)   // 4
#define NBLOCKS  (GRID_X * GRID_Y * NIMG)   // 4096

// SMEM layout (bytes):
//  xyb : 138*48*4 = 26496   bf16x2(x,y) inputs
//  pmu : 138*32*4 = 17664   bf16x2(mu1,mu2) plane
//  pze : 138*32*4 = 17664   bf16x2(z,xy) plane, z = x^2+y^2
#define XYB_BYTES  (SW_H * XY_W * 4)
#define PMU_BYTES  (SW_H * TILE_W * 4)
#define SMEM_BYTES (XYB_BYTES + 2 * PMU_BYTES)   // 61,824 -> 3 CTAs/SM

// Separable Gaussian (sigma=1.5, 11 taps), normalized.
#define W0 0.00102838f
#define W1 0.00759876f
#define W2 0.03600077f
#define W3 0.10936060f
#define W4 0.21300553f
#define W5 0.26601172f
__device__ constexpr float GW[11] = {W0, W1, W2, W3, W4, W5, W4, W3, W2, W1, W0};
#define GPI(t) ((t) < 6 ? (t) : 10 - (t))

typedef unsigned long long ull;

__device__ __forceinline__ ull pack2(float lo, float hi) {
    ull d;
    asm("mov.b64 %0, {%1, %2};" : "=l"(d) : "r"(__float_as_uint(lo)), "r"(__float_as_uint(hi)));
    return d;
}
__device__ __forceinline__ void unpack2(ull v, float& lo, float& hi) {
    unsigned r0, r1;
    asm("mov.b64 {%0, %1}, %2;" : "=r"(r0), "=r"(r1) : "l"(v));
    lo = __uint_as_float(r0); hi = __uint_as_float(r1);
}
__device__ __forceinline__ ull fma2(ull a, ull b, ull c) {
    ull d;
    asm("fma.rn.f32x2 %0, %1, %2, %3;" : "=l"(d) : "l"(a), "l"(b), "l"(c));
    return d;
}
// (lo, hi) floats -> bf16x2 in one 32-bit reg (first asm operand = high half)
__device__ __forceinline__ unsigned b2pack(float lo, float hi) {
    unsigned r;
    asm("cvt.rn.bf16x2.f32 %0, %1, %2;" : "=r"(r) : "f"(hi), "f"(lo));
    return r;
}
// f32x2 (ull) -> bf16x2
__device__ __forceinline__ unsigned cvt_b2(ull v) {
    float lo, hi;
    unpack2(v, lo, hi);
    return b2pack(lo, hi);
}
// bf16x2 -> two f32 (shift/mask: alu ops, no F2F)
__device__ __forceinline__ float2 b2unpack(unsigned r) {
    float2 f;
    f.x = __uint_as_float(r << 16);
    f.y = __uint_as_float(r & 0xffff0000u);
    return f;
}
// bf16x2 -> packed f32x2 (ull)
__device__ __forceinline__ ull b2_to_p2(unsigned r) {
    return pack2(__uint_as_float(r << 16), __uint_as_float(r & 0xffff0000u));
}

__device__ float g_partials[NBLOCKS];
__device__ int   g_count = 0;

extern __shared__ char smem_raw[];

__global__ __launch_bounds__(NTHREADS, 3)
void ssim_fused_kernel(const float* __restrict__ img1, const float* __restrict__ img2,
                       float* __restrict__ out) {
    unsigned* xyb = (unsigned*)smem_raw;                             // 138 x 48 bf16x2(x,y)
    unsigned* pmu = (unsigned*)(smem_raw + XYB_BYTES);               // 138 x 32 bf16x2(mu1,mu2)
    unsigned* pze = (unsigned*)(smem_raw + XYB_BYTES + PMU_BYTES);   // 138 x 32 bf16x2(z,xy)

    const int tid = threadIdx.x;
    const int img = blockIdx.z;
    const int r0  = blockIdx.y * TILE_H;
    const int c0  = blockIdx.x * TILE_W;
    const float* p1 = img1 + (size_t)img * (IMG_H * IMG_W);
    const float* p2 = img2 + (size_t)img * (IMG_H * IMG_W);

    // Packed Gaussian weight pairs for f32x2 conv (both passes)
    ull gp[6];
    gp[0] = pack2(W0, W0); gp[1] = pack2(W1, W1); gp[2] = pack2(W2, W2);
    gp[3] = pack2(W3, W3); gp[4] = pack2(W4, W4); gp[5] = pack2(W5, W5);

    // ---- Load halo strip as bf16x2(x,y): unit = (row, quad of 4 cols) ----
    for (int u = tid; u < SW_H * (XY_W / 4); u += NTHREADS) {
        int r = u / (XY_W / 4);
        int q = u - r * (XY_W / 4);
        int gr = r0 + r - HALO;
        int gc = c0 - PAD_L + q * 4;
        float4 vx = make_float4(0.f, 0.f, 0.f, 0.f);
        float4 vy = vx;
        if (gr >= 0 && gr < IMG_H && gc >= 0 && gc + 3 < IMG_W) {
            vx = *(const float4*)(p1 + (size_t)gr * IMG_W + gc);
            vy = *(const float4*)(p2 + (size_t)gr * IMG_W + gc);
        }
        *(uint4*)(xyb + r * XY_W + q * 4) =
            make_uint4(b2pack(vx.x, vy.x), b2pack(vx.y, vy.y),
                       b2pack(vx.z, vy.z), b2pack(vx.w, vy.w));
    }
    __syncthreads();

    // ---- Horizontal pass: unit = (row, 4 output cols); 138*8 = 1104 units ----
    // Smem col s holds input col s-8. Output j (col cb+j) taps smem cols
    // cb+j+3..cb+j+13. Load cols cb..cb+19 (5x LDS.128), use k=3..16, t=k-3-j.
    for (int unit = tid; unit < SW_H * (TILE_W / 4); unit += NTHREADS) {
        const int row = unit >> 3;
        const int cb  = (unit & 7) * 4;

        unsigned u[20];
        const uint4* vr = (const uint4*)(xyb + row * XY_W + cb);
        #pragma unroll
        for (int i = 0; i < 5; i++) {
            uint4 t = vr[i];
            u[4*i+0] = t.x; u[4*i+1] = t.y; u[4*i+2] = t.z; u[4*i+3] = t.w;
        }

        const int o = row * TILE_W + cb;

        // Sweep A: packed (mu1,mu2) conv
        {
            ull mu[4] = {0, 0, 0, 0};
            #pragma unroll
            for (int k = 3; k < 17; k++) {
                const ull w = b2_to_p2(u[k]);
                #pragma unroll
                for (int j = 0; j < 4; j++) {
                    const int t = k - 3 - j;
                    if (t >= 0 && t < 11)
                        mu[j] = fma2(gp[GPI(t)], w, mu[j]);
                }
            }
            *(uint4*)(pmu + o) = make_uint4(cvt_b2(mu[0]), cvt_b2(mu[1]),
                                            cvt_b2(mu[2]), cvt_b2(mu[3]));
        }
        // Sweep B: packed (z, xy) conv, z = x^2 + y^2
        {
            ull sz[4] = {0, 0, 0, 0};
            #pragma unroll
            for (int k = 3; k < 17; k++) {
                const float2 f = b2unpack(u[k]);
                const float e = f.x * f.y;
                const float z = fmaf(f.x, f.x, f.y * f.y);
                const ull w = pack2(z, e);
                #pragma unroll
                for (int j = 0; j < 4; j++) {
                    const int t = k - 3 - j;
                    if (t >= 0 && t < 11)
                        sz[j] = fma2(gp[GPI(t)], w, sz[j]);
                }
            }
            *(uint4*)(pze + o) = make_uint4(cvt_b2(sz[0]), cvt_b2(sz[1]),
                                            cvt_b2(sz[2]), cvt_b2(sz[3]));
        }
    }
    __syncthreads();

    // ---- Vertical pass + SSIM: 16 groups x 32 cols, 8 rows/thread ----
    float local = 0.f;
    const int col = tid & (TILE_W - 1);
    const int rb  = (tid >> 5) * 8;     // output rows rb..rb+7; taps rb..rb+17

    const float C1 = 0.0001f;
    const float C2 = 0.0009f;

    {
        // Sweep 1: (mu1,mu2) packed accumulation -> fold to P, S
        float P[8], S[8];
        {
            ull amu[8] = {0,0,0,0,0,0,0,0};
            const unsigned* src = pmu + rb * TILE_W + col;
            #pragma unroll
            for (int k = 0; k < 18; k++) {
                const ull w = b2_to_p2(src[k * TILE_W]);
                #pragma unroll
                for (int j = 0; j < 8; j++) {
                    const int t = k - j;
                    if (t >= 0 && t < 11)
                        amu[j] = fma2(gp[GPI(t)], w, amu[j]);
                }
            }
            #pragma unroll
            for (int j = 0; j < 8; j++) {
                float mu1, mu2;
                unpack2(amu[j], mu1, mu2);
                P[j] = mu1 * mu2;
                S[j] = fmaf(mu1, mu1, mu2 * mu2);
            }
        }

        // Sweep 2: (z, xy) packed accumulation -> SSIM
        {
            ull asz[8] = {0,0,0,0,0,0,0,0};
            const unsigned* src = pze + rb * TILE_W + col;
            #pragma unroll
            for (int k = 0; k < 18; k++) {
                const ull w = b2_to_p2(src[k * TILE_W]);
                #pragma unroll
                for (int j = 0; j < 8; j++) {
                    const int t = k - j;
                    if (t >= 0 && t < 11)
                        asz[j] = fma2(gp[GPI(t)], w, asz[j]);
                }
            }
            #pragma unroll
            for (int j = 0; j < 8; j++) {
                float z, e;
                unpack2(asz[j], z, e);
                const float s12 = e - P[j];                // sigma12
                const float sig = z - S[j];                // sigma1^2 + sigma2^2
                const float num = (2.f * P[j] + C1) * (2.f * s12 + C2);
                const float den = (S[j] + C1) * (sig + C2);
                local += __fdividef(num, den);
            }
        }
    }

    // ---- Block reduction (fixed order -> deterministic) ----
    #pragma unroll
    for (int off = 16; off > 0; off >>= 1)
        local += __shfl_xor_sync(0xffffffffu, local, off);

    __shared__ float wsum[NTHREADS / 32];
    __shared__ int   s_last;
    if ((tid & 31) == 0) wsum[tid >> 5] = local;
    __syncthreads();
    if (tid == 0) {
        float s = 0.f;
        #pragma unroll
        for (int w = 0; w < NTHREADS / 32; w++) s += wsum[w];
        int bid = (blockIdx.z * gridDim.y + blockIdx.y) * gridDim.x + blockIdx.x;
        g_partials[bid] = s;
        __threadfence();
        int old = atomicAdd(&g_count, 1);
        s_last = (old == NBLOCKS - 1);
    }
    __syncthreads();

    // ---- Last block: deterministic final reduction in fp64, reset counter ----
    if (s_last) {
        __threadfence();
        __shared__ double dsh[NTHREADS / 32];
        double acc = 0.0;
        const int per = NBLOCKS / NTHREADS;   // 8
        for (int i = 0; i < per; i++)
            acc += (double)g_partials[tid * per + i];
        #pragma unroll
        for (int off = 16; off > 0; off >>= 1)
            acc += __shfl_xor_sync(0xffffffffu, acc, off);
        if ((tid & 31) == 0) dsh[tid >> 5] = acc;
        __syncthreads();
        if (tid == 0) {
            double s = 0.0;
            #pragma unroll
            for (int w = 0; w < NTHREADS / 32; w++) s += dsh[w];
            out[0] = (float)(1.0 - s * (1.0 / (double)NPIX));
            g_count = 0;   // reset for next graph replay
        }
    }
}

extern "C" void kernel_launch(void* const* d_in, const int* in_sizes, int n_in,
                              void* d_out, int out_size) {
    const float* pred   = (const float*)d_in[0];
    const float* target = (const float*)d_in[1];
    float* out = (float*)d_out;

    cudaFuncSetAttribute(ssim_fused_kernel,
                         cudaFuncAttributeMaxDynamicSharedMemorySize, SMEM_BYTES);

    dim3 grid(GRID_X, GRID_Y, NIMG);   // (16, 4, 64)
    ssim_fused_kernel<<<grid, NTHREADS, SMEM_BYTES>>>(pred, target, out);
}

// round 16
// speedup vs baseline: 2.1208x; 1.0092x over previous
#include <cuda_runtime.h>

// Problem constants
#define IMG_H 512
#define IMG_W 512
#define NIMG  64
#define NPIX  (NIMG * IMG_H * IMG_W)   // 16,777,216

#define TILE_W   32
#define TILE_H   128
#define HALO     5
#define SW_H     138         // TILE_H + 2*HALO
#define PAD_L    8           // left pad (>= HALO, quad aligned)
#define XY_W     48          // strip width in elems (12 quads)
#define NTHREADS 512
#define GRID_X   (IMG_W / TILE_W)   // 16
#define GRID_Y   (IMG_H / TILE_H)   // 4
#define NBLOCKS  (GRID_X * GRID_Y * NIMG)   // 4096

// SMEM layout (bytes):
//  xyb : 138*48*4 = 26496   bf16x2(x,y) inputs
//  pmu : 138*32*4 = 17664   bf16x2(mu1,mu2) plane
//  pze : 138*32*4 = 17664   bf16x2(z,xy) plane, z = x^2+y^2
#define XYB_BYTES  (SW_H * XY_W * 4)
#define PMU_BYTES  (SW_H * TILE_W * 4)
#define SMEM_BYTES (XYB_BYTES + 2 * PMU_BYTES)   // 61,824 -> 3 CTAs/SM

// Separable Gaussian (sigma=1.5, 11 taps), normalized.
#define W0 0.00102838f
#define W1 0.00759876f
#define W2 0.03600077f
#define W3 0.10936060f
#define W4 0.21300553f
#define W5 0.26601172f
__device__ constexpr float GW[11] = {W0, W1, W2, W3, W4, W5, W4, W3, W2, W1, W0};
#define GPI(t) ((t) < 6 ? (t) : 10 - (t))

typedef unsigned long long ull;

__device__ __forceinline__ ull pack2(float lo, float hi) {
    ull d;
    asm("mov.b64 %0, {%1, %2};" : "=l"(d) : "r"(__float_as_uint(lo)), "r"(__float_as_uint(hi)));
    return d;
}
__device__ __forceinline__ void unpack2(ull v, float& lo, float& hi) {
    unsigned r0, r1;
    asm("mov.b64 {%0, %1}, %2;" : "=r"(r0), "=r"(r1) : "l"(v));
    lo = __uint_as_float(r0); hi = __uint_as_float(r1);
}
__device__ __forceinline__ ull fma2(ull a, ull b, ull c) {
    ull d;
    asm("fma.rn.f32x2 %0, %1, %2, %3;" : "=l"(d) : "l"(a), "l"(b), "l"(c));
    return d;
}
// (lo, hi) floats -> bf16x2 in one 32-bit reg (first asm operand = high half)
__device__ __forceinline__ unsigned b2pack(float lo, float hi) {
    unsigned r;
    asm("cvt.rn.bf16x2.f32 %0, %1, %2;" : "=r"(r) : "f"(hi), "f"(lo));
    return r;
}
// f32x2 (ull) -> bf16x2
__device__ __forceinline__ unsigned cvt_b2(ull v) {
    float lo, hi;
    unpack2(v, lo, hi);
    return b2pack(lo, hi);
}
// bf16x2 -> two f32 (shift/mask: alu ops, no F2F)
__device__ __forceinline__ float2 b2unpack(unsigned r) {
    float2 f;
    f.x = __uint_as_float(r << 16);
    f.y = __uint_as_float(r & 0xffff0000u);
    return f;
}
// bf16x2 -> packed f32x2 (ull)
__device__ __forceinline__ ull b2_to_p2(unsigned r) {
    return pack2(__uint_as_float(r << 16), __uint_as_float(r & 0xffff0000u));
}

__device__ float g_partials[NBLOCKS];
__device__ int   g_count = 0;

extern __shared__ char smem_raw[];

__global__ __launch_bounds__(NTHREADS, 3)
void ssim_fused_kernel(const float* __restrict__ img1, const float* __restrict__ img2,
                       float* __restrict__ out) {
    unsigned* xyb = (unsigned*)smem_raw;                             // 138 x 48 bf16x2(x,y)
    unsigned* pmu = (unsigned*)(smem_raw + XYB_BYTES);               // 138 x 32 bf16x2(mu1,mu2)
    unsigned* pze = (unsigned*)(smem_raw + XYB_BYTES + PMU_BYTES);   // 138 x 32 bf16x2(z,xy)

    const int tid = threadIdx.x;
    const int img = blockIdx.z;
    const int r0  = blockIdx.y * TILE_H;
    const int c0  = blockIdx.x * TILE_W;
    const float* p1 = img1 + (size_t)img * (IMG_H * IMG_W);
    const float* p2 = img2 + (size_t)img * (IMG_H * IMG_W);

    // Packed Gaussian weight pairs for f32x2 conv (both passes)
    ull gp[6];
    gp[0] = pack2(W0, W0); gp[1] = pack2(W1, W1); gp[2] = pack2(W2, W2);
    gp[3] = pack2(W3, W3); gp[4] = pack2(W4, W4); gp[5] = pack2(W5, W5);

    // ---- Load halo strip as bf16x2(x,y): unit = (row, quad of 4 cols) ----
    for (int u = tid; u < SW_H * (XY_W / 4); u += NTHREADS) {
        int r = u / (XY_W / 4);
        int q = u - r * (XY_W / 4);
        int gr = r0 + r - HALO;
        int gc = c0 - PAD_L + q * 4;
        float4 vx = make_float4(0.f, 0.f, 0.f, 0.f);
        float4 vy = vx;
        if (gr >= 0 && gr < IMG_H && gc >= 0 && gc + 3 < IMG_W) {
            vx = *(const float4*)(p1 + (size_t)gr * IMG_W + gc);
            vy = *(const float4*)(p2 + (size_t)gr * IMG_W + gc);
        }
        *(uint4*)(xyb + r * XY_W + q * 4) =
            make_uint4(b2pack(vx.x, vy.x), b2pack(vx.y, vy.y),
                       b2pack(vx.z, vy.z), b2pack(vx.w, vy.w));
    }
    __syncthreads();

    // ---- Horizontal pass (single merged streaming sweep) ----
    // unit = (row, 4 output cols); 138*8 = 1104 units.
    // Smem col s holds input col s-8. Output j (col cb+j) taps smem cols
    // cb+j+3..cb+j+13. Stream chunks covering cols cb..cb+19; consume each
    // value ONCE: unpack -> (z,e) -> feed both accumulator sets.
    for (int unit = tid; unit < SW_H * (TILE_W / 4); unit += NTHREADS) {
        const int row = unit >> 3;
        const int cb  = (unit & 7) * 4;

        const uint4* vr = (const uint4*)(xyb + row * XY_W + cb);

        ull mu[4] = {0, 0, 0, 0};
        ull sz[4] = {0, 0, 0, 0};

        #pragma unroll
        for (int i = 0; i < 5; i++) {
            const uint4 chunk = vr[i];
            const unsigned cw[4] = {chunk.x, chunk.y, chunk.z, chunk.w};
            #pragma unroll
            for (int c = 0; c < 4; c++) {
                const int k = 4 * i + c;
                if (k >= 3 && k <= 16) {           // valid tap columns
                    const float2 f = b2unpack(cw[c]);
                    const ull wxy = pack2(f.x, f.y);
                    const float e = f.x * f.y;
                    const float z = fmaf(f.x, f.x, f.y * f.y);
                    const ull wze = pack2(z, e);
                    #pragma unroll
                    for (int j = 0; j < 4; j++) {
                        const int t = k - 3 - j;
                        if (t >= 0 && t < 11) {
                            const ull g = gp[GPI(t)];
                            mu[j] = fma2(g, wxy, mu[j]);
                            sz[j] = fma2(g, wze, sz[j]);
                        }
                    }
                }
            }
        }

        const int o = row * TILE_W + cb;
        *(uint4*)(pmu + o) = make_uint4(cvt_b2(mu[0]), cvt_b2(mu[1]),
                                        cvt_b2(mu[2]), cvt_b2(mu[3]));
        *(uint4*)(pze + o) = make_uint4(cvt_b2(sz[0]), cvt_b2(sz[1]),
                                        cvt_b2(sz[2]), cvt_b2(sz[3]));
    }
    __syncthreads();

    // ---- Vertical pass + SSIM: 16 groups x 32 cols, 8 rows/thread ----
    float local = 0.f;
    const int col = tid & (TILE_W - 1);
    const int rb  = (tid >> 5) * 8;     // output rows rb..rb+7; taps rb..rb+17

    const float C1 = 0.0001f;
    const float C2 = 0.0009f;

    {
        // Sweep 1: (mu1,mu2) packed accumulation -> fold to P, S
        float P[8], S[8];
        {
            ull amu[8] = {0,0,0,0,0,0,0,0};
            const unsigned* src = pmu + rb * TILE_W + col;
            #pragma unroll
            for (int k = 0; k < 18; k++) {
                const ull w = b2_to_p2(src[k * TILE_W]);
                #pragma unroll
                for (int j = 0; j < 8; j++) {
                    const int t = k - j;
                    if (t >= 0 && t < 11)
                        amu[j] = fma2(gp[GPI(t)], w, amu[j]);
                }
            }
            #pragma unroll
            for (int j = 0; j < 8; j++) {
                float mu1, mu2;
                unpack2(amu[j], mu1, mu2);
                P[j] = mu1 * mu2;
                S[j] = fmaf(mu1, mu1, mu2 * mu2);
            }
        }

        // Sweep 2: (z, xy) packed accumulation -> SSIM
        {
            ull asz[8] = {0,0,0,0,0,0,0,0};
            const unsigned* src = pze + rb * TILE_W + col;
            #pragma unroll
            for (int k = 0; k < 18; k++) {
                const ull w = b2_to_p2(src[k * TILE_W]);
                #pragma unroll
                for (int j = 0; j < 8; j++) {
                    const int t = k - j;
                    if (t >= 0 && t < 11)
                        asz[j] = fma2(gp[GPI(t)], w, asz[j]);
                }
            }
            #pragma unroll
            for (int j = 0; j < 8; j++) {
                float z, e;
                unpack2(asz[j], z, e);
                const float s12 = e - P[j];                // sigma12
                const float sig = z - S[j];                // sigma1^2 + sigma2^2
                const float num = (2.f * P[j] + C1) * (2.f * s12 + C2);
                const float den = (S[j] + C1) * (sig + C2);
                local += __fdividef(num, den);
            }
        }
    }

    // ---- Block reduction (fixed order -> deterministic) ----
    #pragma unroll
    for (int off = 16; off > 0; off >>= 1)
        local += __shfl_xor_sync(0xffffffffu, local, off);

    __shared__ float wsum[NTHREADS / 32];
    __shared__ int   s_last;
    if ((tid & 31) == 0) wsum[tid >> 5] = local;
    __syncthreads();
    if (tid == 0) {
        float s = 0.f;
        #pragma unroll
        for (int w = 0; w < NTHREADS / 32; w++) s += wsum[w];
        int bid = (blockIdx.z * gridDim.y + blockIdx.y) * gridDim.x + blockIdx.x;
        g_partials[bid] = s;
        __threadfence();
        int old = atomicAdd(&g_count, 1);
        s_last = (old == NBLOCKS - 1);
    }
    __syncthreads();

    // ---- Last block: deterministic final reduction in fp64, reset counter ----
    if (s_last) {
        __threadfence();
        __shared__ double dsh[NTHREADS / 32];
        double acc = 0.0;
        const int per = NBLOCKS / NTHREADS;   // 8
        for (int i = 0; i < per; i++)
            acc += (double)g_partials[tid * per + i];
        #pragma unroll
        for (int off = 16; off > 0; off >>= 1)
            acc += __shfl_xor_sync(0xffffffffu, acc, off);
        if ((tid & 31) == 0) dsh[tid >> 5] = acc;
        __syncthreads();
        if (tid == 0) {
            double s = 0.0;
            #pragma unroll
            for (int w = 0; w < NTHREADS / 32; w++) s += dsh[w];
            out[0] = (float)(1.0 - s * (1.0 / (double)NPIX));
            g_count = 0;   // reset for next graph replay
        }
    }
}

extern "C" void kernel_launch(void* const* d_in, const int* in_sizes, int n_in,
                              void* d_out, int out_size) {
    const float* pred   = (const float*)d_in[0];
    const float* target = (const float*)d_in[1];
    float* out = (float*)d_out;

    cudaFuncSetAttribute(ssim_fused_kernel,
                         cudaFuncAttributeMaxDynamicSharedMemorySize, SMEM_BYTES);

    dim3 grid(GRID_X, GRID_Y, NIMG);   // (16, 4, 64)
    ssim_fused_kernel<<<grid, NTHREADS, SMEM_BYTES>>>(pred, target, out);
}